// round 1
// baseline (speedup 1.0000x reference)
#include <cuda_runtime.h>
#include <cstdint>

// Problem constants (from reference setup_inputs): B=8192, O=64, D=64, K=64
#define BB   8192
#define OO   64
#define DD   64
#define KK   64
#define JJN  65            // 0 = left-linear, 1..63 = cubic intervals, 64 = right-linear
#define PD   (JJN * OO)    // float4 slots per d-slice = 4160
#define BT   512           // b-tile per CTA
#define NDC  8             // number of d-chunks (split-K over d)
#define DCH  (DD / NDC)    // d per chunk = 8
#define NBT  (BB / BT)     // 16 b-tiles

// Static device scratch (allocation-free rule)
__device__ float4 g_P[DD * PD];                 // [d][jj][o] cubic coeffs, 4.26 MB
__device__ float  g_xT[DD * BB];                // transposed x, 2 MB
__device__ float  g_part[NDC * BB * OO];        // split-K partials, 16 MB

// ---------------------------------------------------------------- cp.async
__device__ __forceinline__ void cp_async16(uint32_t dst, const void* src) {
    asm volatile("cp.async.cg.shared.global [%0], [%1], 16;\n" :: "r"(dst), "l"(src));
}
__device__ __forceinline__ void cp_async_commit() { asm volatile("cp.async.commit_group;\n"); }
__device__ __forceinline__ void cp_async_wait0()  { asm volatile("cp.async.wait_group 0;\n"); }

// ---------------------------------------------------------------- transpose x -> xT
__global__ void kan_transpose(const float* __restrict__ x, float* __restrict__ xT) {
    __shared__ float tile[32][33];
    int bx = blockIdx.x;           // 256 b-tiles of 32
    int by = blockIdx.y;           // 2 d-tiles of 32
    int tx = threadIdx.x, ty = threadIdx.y;   // (32, 8)
    #pragma unroll
    for (int i = 0; i < 4; i++)
        tile[ty + i * 8][tx] = x[(bx * 32 + ty + i * 8) * DD + by * 32 + tx];
    __syncthreads();
    #pragma unroll
    for (int i = 0; i < 4; i++)
        xT[(by * 32 + ty + i * 8) * BB + bx * 32 + tx] = tile[tx][ty + i * 8];
}

// ---------------------------------------------------------------- prep: slopes + cubic coeffs
// One CTA per d. sy[k*65+o] holds coeffs[o,d,k]; slopes computed with deltas on the fly.
__global__ void kan_prep(const float* __restrict__ coeffs) {
    __shared__ float sy[KK * 65];   // padded rows (store phase conflict-free)
    __shared__ float ss[KK * OO];   // slopes

    const int d = blockIdx.x;
    const int tid = threadIdx.x;
    const float inv_h = 15.75f;           // (K-1)/(X_MAX-X_MIN) = 63/4, exact
    const float h = 4.0f / 63.0f;

    // load coeffs[:, d, :] (coalesced per o-row), store transposed
    for (int e = tid; e < OO * KK; e += 256) {
        int o = e >> 6, k = e & 63;
        sy[k * 65 + o] = coeffs[(o << 12) + (d << 6) + k];
    }
    __syncthreads();

    // PCHIP slopes (matches reference incl. endpoint fixups and 1e-12 guard)
    for (int e = tid; e < KK * OO; e += 256) {
        int k = e >> 6, o = e & 63;
        float s;
        if (k == 0) {
            float d0 = (sy[1 * 65 + o] - sy[0 * 65 + o]) * inv_h;
            float d1 = (sy[2 * 65 + o] - sy[1 * 65 + o]) * inv_h;
            s = 0.5f * (3.0f * d0 - d1);
            if (s * d0 <= 0.0f) s = 0.0f;
            else if (d0 * d1 < 0.0f && fabsf(s) > 3.0f * fabsf(d0)) s = 3.0f * d0;
        } else if (k == 63) {
            float dN = (sy[63 * 65 + o] - sy[62 * 65 + o]) * inv_h;
            float dM = (sy[62 * 65 + o] - sy[61 * 65 + o]) * inv_h;
            s = 0.5f * (3.0f * dN - dM);
            if (s * dN <= 0.0f) s = 0.0f;
            else if (dN * dM < 0.0f && fabsf(s) > 3.0f * fabsf(dN)) s = 3.0f * dN;
        } else {
            float dp = (sy[k * 65 + o] - sy[(k - 1) * 65 + o]) * inv_h;
            float dn = (sy[(k + 1) * 65 + o] - sy[k * 65 + o]) * inv_h;
            s = (dp * dn > 0.0f) ? (2.0f * dp * dn / (dp + dn + 1e-12f)) : 0.0f;
        }
        ss[k * OO + o] = s;
    }
    __syncthreads();

    // emit per-interval cubic (or linear extrapolation) coefficients
    float4* Pd = g_P + d * PD;
    for (int e = tid; e < PD; e += 256) {
        int jj = e >> 6, o = e & 63;
        float4 p;
        if (jj == 0) {
            p = make_float4(sy[o], h * ss[o], 0.0f, 0.0f);
        } else if (jj == 64) {
            p = make_float4(sy[63 * 65 + o], h * ss[63 * OO + o], 0.0f, 0.0f);
        } else {
            int j = jj - 1;
            float y0 = sy[j * 65 + o],       y1 = sy[(j + 1) * 65 + o];
            float m0 = h * ss[j * OO + o],   m1 = h * ss[(j + 1) * OO + o];
            p.x = y0;
            p.y = m0;
            p.z = -3.0f * y0 + 3.0f * y1 - 2.0f * m0 - m1;
            p.w =  2.0f * y0 - 2.0f * y1 + m0 + m1;
        }
        Pd[e] = p;
    }
}

// ---------------------------------------------------------------- main contraction
// grid (NBT, NDC), 512 threads = 16 warps. Warp handles 32 b's, lanes index o (o, o+32).
// Per d: 66.5 KB P-slice staged in smem (cp.async double buffered), uniform-jj LDS.128 gathers.
__global__ __launch_bounds__(512, 1) void kan_main(const float* __restrict__ xT,
                                                   float* __restrict__ part) {
    extern __shared__ float4 sP[];          // 2 x PD float4
    const int bt = blockIdx.x, dc = blockIdx.y;
    const int tid = threadIdx.x;
    const int w = tid >> 5, lane = tid & 31;
    const int b0 = bt * BT + w * 32;
    const int dbase = dc * DCH;

    float4* buf0 = sP;
    float4* buf1 = sP + PD;
    uint32_t sb = (uint32_t)__cvta_generic_to_shared(sP);

    // stage d-slice dd into buffer (async)
    auto stage = [&](int dd, int which) {
        const float4* src = g_P + (size_t)(dbase + dd) * PD;
        uint32_t dst = sb + (uint32_t)which * (PD * 16);
        for (int e = tid; e < PD; e += 512)
            cp_async16(dst + e * 16, src + e);
        cp_async_commit();
    };

    stage(0, 0);

    float acc0[32], acc1[32];
    #pragma unroll
    for (int i = 0; i < 32; i++) { acc0[i] = 0.0f; acc1[i] = 0.0f; }

    cp_async_wait0();
    __syncthreads();

    for (int dd = 0; dd < DCH; dd++) {
        float4* cur = (dd & 1) ? buf1 : buf0;
        if (dd + 1 < DCH) stage(dd + 1, (dd + 1) & 1);

        // each lane computes (jj, u) for its own b; broadcast via shuffle in i-loop
        float xv = xT[(dbase + dd) * BB + b0 + lane];
        float t = (xv + 2.0f) * 15.75f;
        float f = fminf(fmaxf(floorf(t), 0.0f), 62.0f);
        int jj; float u;
        if (t < 0.0f)       { jj = 0;  u = t; }
        else if (t > 63.0f) { jj = 64; u = t - 63.0f; }
        else                { jj = (int)f + 1; u = t - f; }
        int off = jj << 6;  // float4 offset of row

        #pragma unroll
        for (int i = 0; i < 32; i++) {
            int   oi = __shfl_sync(0xffffffffu, off, i);
            float ui = __shfl_sync(0xffffffffu, u,   i);
            const float4* row = cur + oi + lane;
            float4 a = row[0];
            float4 c = row[32];
            acc0[i] += ((a.w * ui + a.z) * ui + a.y) * ui + a.x;
            acc1[i] += ((c.w * ui + c.z) * ui + c.y) * ui + c.x;
        }

        cp_async_wait0();
        __syncthreads();
    }

    // write split-K partials: part[dc][b][o]
    float* pdst = part + ((size_t)dc * BB + b0) * OO;
    #pragma unroll
    for (int i = 0; i < 32; i++) {
        pdst[i * OO + lane]      = acc0[i];
        pdst[i * OO + 32 + lane] = acc1[i];
    }
}

// ---------------------------------------------------------------- split-K reduce + bias
__global__ void kan_reduce(const float* __restrict__ part, const float* __restrict__ bias,
                           float* __restrict__ out) {
    int idx = blockIdx.x * 256 + threadIdx.x;   // over B*O
    float s = bias[idx & (OO - 1)];
    #pragma unroll
    for (int c = 0; c < NDC; c++) s += part[c * (BB * OO) + idx];
    out[idx] = s;
}

// ---------------------------------------------------------------- launch
extern "C" void kernel_launch(void* const* d_in, const int* in_sizes, int n_in,
                              void* d_out, int out_size) {
    const float* x      = (const float*)d_in[0];   // [8192, 64]
    const float* coeffs = (const float*)d_in[1];   // [64, 64, 64]
    const float* bias   = (const float*)d_in[2];   // [64]
    float* out = (float*)d_out;                    // [8192, 64]

    float4* Pp;   cudaGetSymbolAddress((void**)&Pp, g_P);
    float*  xTp;  cudaGetSymbolAddress((void**)&xTp, g_xT);
    float*  prt;  cudaGetSymbolAddress((void**)&prt, g_part);

    cudaFuncSetAttribute(kan_main, cudaFuncAttributeMaxDynamicSharedMemorySize,
                         2 * PD * (int)sizeof(float4));

    dim3 tgrid(BB / 32, DD / 32);
    kan_transpose<<<tgrid, dim3(32, 8)>>>(x, xTp);
    kan_prep<<<DD, 256>>>(coeffs);

    dim3 mgrid(NBT, NDC);
    kan_main<<<mgrid, 512, 2 * PD * (int)sizeof(float4)>>>(xTp, prt);

    kan_reduce<<<(BB * OO) / 256, 256>>>(prt, bias, out);
}

// round 4
// speedup vs baseline: 1.2931x; 1.2931x over previous
#include <cuda_runtime.h>
#include <cuda_fp16.h>
#include <cstdint>

// Problem constants: B=8192, O=64, D=64, K=64
#define BB   8192
#define OO   64
#define DD   64
#define KK   64
#define JJN  65                 // 0 = left-linear, 1..63 cubic, 64 = right-linear
#define SLICE (JJN * 32)        // uint4 entries per d-slice = 2080 (fp16-packed, o-pairs)
#define NDC  4                  // d-chunks (split-K)
#define DCH  (DD / NDC)         // 16
#define BT   256                // b-tile per CTA
#define NBT  (BB / BT)          // 32

typedef unsigned long long u64;

// Static device scratch
__device__ uint4 g_Ph[DD * SLICE];        // packed cubic coeffs, 2.13 MB
__device__ float g_part[NDC * BB * OO];   // split-K partials, 8 MB

// ---------------------------------------------------------------- asm helpers
__device__ __forceinline__ void cp_async16(uint32_t dst, const void* src) {
    asm volatile("cp.async.cg.shared.global [%0], [%1], 16;\n" :: "r"(dst), "l"(src));
}
__device__ __forceinline__ void cp_async_commit() { asm volatile("cp.async.commit_group;\n"); }
__device__ __forceinline__ void cp_async_wait0()  { asm volatile("cp.async.wait_group 0;\n"); }

__device__ __forceinline__ u64 pk2(float a, float b) {
    u64 r; asm("mov.b64 %0, {%1, %2};" : "=l"(r) : "f"(a), "f"(b)); return r;
}
__device__ __forceinline__ float2 upk2(u64 a) {
    float2 r; asm("mov.b64 {%0, %1}, %2;" : "=f"(r.x), "=f"(r.y) : "l"(a)); return r;
}
__device__ __forceinline__ u64 fma2(u64 a, u64 b, u64 c) {
    u64 d; asm("fma.rn.f32x2 %0, %1, %2, %3;" : "=l"(d) : "l"(a), "l"(b), "l"(c)); return d;
}
__device__ __forceinline__ u64 add2(u64 a, u64 b) {
    u64 d; asm("add.rn.f32x2 %0, %1, %2;" : "=l"(d) : "l"(a), "l"(b)); return d;
}

// ---------------------------------------------------------------- prep: slopes + packed cubic coeffs
// One CTA per d. Matches reference PCHIP exactly (incl. endpoint fixups, 1e-12 guard).
__global__ void kan_prep(const float* __restrict__ coeffs) {
    __shared__ float sy[KK * 65];   // y transposed, padded rows
    __shared__ float ss[KK * OO];   // slopes

    const int d = blockIdx.x;
    const int tid = threadIdx.x;
    const float inv_h = 15.75f;     // 63/4 exact
    const float h = 4.0f / 63.0f;

    for (int e = tid; e < OO * KK; e += 256) {
        int o = e >> 6, k = e & 63;
        sy[k * 65 + o] = coeffs[(o << 12) + (d << 6) + k];
    }
    __syncthreads();

    for (int e = tid; e < KK * OO; e += 256) {
        int k = e >> 6, o = e & 63;
        float s;
        if (k == 0) {
            float d0 = (sy[1 * 65 + o] - sy[0 * 65 + o]) * inv_h;
            float d1 = (sy[2 * 65 + o] - sy[1 * 65 + o]) * inv_h;
            s = 0.5f * (3.0f * d0 - d1);
            if (s * d0 <= 0.0f) s = 0.0f;
            else if (d0 * d1 < 0.0f && fabsf(s) > 3.0f * fabsf(d0)) s = 3.0f * d0;
        } else if (k == 63) {
            float dN = (sy[63 * 65 + o] - sy[62 * 65 + o]) * inv_h;
            float dM = (sy[62 * 65 + o] - sy[61 * 65 + o]) * inv_h;
            s = 0.5f * (3.0f * dN - dM);
            if (s * dN <= 0.0f) s = 0.0f;
            else if (dN * dM < 0.0f && fabsf(s) > 3.0f * fabsf(dN)) s = 3.0f * dN;
        } else {
            float dp = (sy[k * 65 + o] - sy[(k - 1) * 65 + o]) * inv_h;
            float dn = (sy[(k + 1) * 65 + o] - sy[k * 65 + o]) * inv_h;
            s = (dp * dn > 0.0f) ? (2.0f * dp * dn / (dp + dn + 1e-12f)) : 0.0f;
        }
        ss[k * OO + o] = s;
    }
    __syncthreads();

    // per-interval cubic (or linear extrapolation) coefficients, fp16 pair-packed
    auto evalP = [&](int jj, int o) -> float4 {
        float4 p;
        if (jj == 0) {
            p = make_float4(sy[o], h * ss[o], 0.0f, 0.0f);
        } else if (jj == 64) {
            p = make_float4(sy[63 * 65 + o], h * ss[63 * OO + o], 0.0f, 0.0f);
        } else {
            int j = jj - 1;
            float y0 = sy[j * 65 + o],     y1 = sy[(j + 1) * 65 + o];
            float m0 = h * ss[j * OO + o], m1 = h * ss[(j + 1) * OO + o];
            p.x = y0;
            p.y = m0;
            p.z = -3.0f * y0 + 3.0f * y1 - 2.0f * m0 - m1;
            p.w =  2.0f * y0 - 2.0f * y1 + m0 + m1;
        }
        return p;
    };

    uint4* Pd = g_Ph + d * SLICE;
    for (int e = tid; e < SLICE; e += 256) {
        int jj = e >> 5, o = e & 31;
        float4 a = evalP(jj, o);
        float4 b = evalP(jj, o + 32);
        __half2 h0 = __floats2half2_rn(a.x, b.x);
        __half2 h1 = __floats2half2_rn(a.y, b.y);
        __half2 h2 = __floats2half2_rn(a.z, b.z);
        __half2 h3 = __floats2half2_rn(a.w, b.w);
        uint4 q;
        q.x = *reinterpret_cast<uint32_t*>(&h0);
        q.y = *reinterpret_cast<uint32_t*>(&h1);
        q.z = *reinterpret_cast<uint32_t*>(&h2);
        q.w = *reinterpret_cast<uint32_t*>(&h3);
        Pd[e] = q;
    }
}

// ---------------------------------------------------------------- main contraction
// grid (NBT, NDC) = (32, 4) = 128 CTAs, 512 threads = 16 warps.
// Warp handles 16 b's; lanes index o-pair (o, o+32) via fp16-packed uint4 rows.
__global__ __launch_bounds__(512, 1) void kan_main(const float* __restrict__ x,
                                                   float* __restrict__ part) {
    extern __shared__ char smraw[];
    uint4* sP = reinterpret_cast<uint4*>(smraw);                  // 2 * SLICE uint4
    float* sx = reinterpret_cast<float*>(smraw + 2 * SLICE * 16); // DCH * BT floats

    const int bt = blockIdx.x, dc = blockIdx.y;
    const int tid = threadIdx.x;
    const int w = tid >> 5, lane = tid & 31;
    const int dbase = dc * DCH;
    const int b0g = bt * BT;

    // load x tile [BT][DCH] -> sx[dd][b_local]
    for (int e = tid; e < BT * 4; e += 512) {
        int bl = e >> 2, seg = e & 3;
        float4 v = *reinterpret_cast<const float4*>(x + (size_t)(b0g + bl) * DD + dbase + seg * 4);
        sx[(seg * 4 + 0) * BT + bl] = v.x;
        sx[(seg * 4 + 1) * BT + bl] = v.y;
        sx[(seg * 4 + 2) * BT + bl] = v.z;
        sx[(seg * 4 + 3) * BT + bl] = v.w;
    }

    uint32_t sb = (uint32_t)__cvta_generic_to_shared(sP);
    auto stage = [&](int dd, int which) {
        const uint4* src = g_Ph + (size_t)(dbase + dd) * SLICE;
        uint32_t dst = sb + (uint32_t)which * (SLICE * 16);
        for (int e = tid; e < SLICE; e += 512)
            cp_async16(dst + e * 16, src + e);
        cp_async_commit();
    };

    stage(0, 0);

    u64 acc[16];
    #pragma unroll
    for (int i = 0; i < 16; i++) acc[i] = 0ULL;   // bit pattern of (0.f, 0.f)

    cp_async_wait0();
    __syncthreads();   // covers sx stores too

    for (int dd = 0; dd < DCH; dd++) {
        uint4* cur = sP + (dd & 1) * SLICE;
        if (dd + 1 < DCH) stage(dd + 1, (dd + 1) & 1);

        // (jj, u) for this warp's 16 b's (lanes 16-31 mirror 0-15)
        float xv = sx[dd * BT + (w << 4) + (lane & 15)];
        float t = (xv + 2.0f) * 15.75f;
        float f = fminf(fmaxf(floorf(t), 0.0f), 62.0f);
        int jj; float u;
        if (t < 0.0f)       { jj = 0;  u = t; }
        else if (t > 63.0f) { jj = 64; u = t - 63.0f; }
        else                { jj = (int)f + 1; u = t - f; }
        int off = jj << 5;

        #pragma unroll
        for (int i = 0; i < 16; i++) {
            int   oi = __shfl_sync(0xffffffffu, off, i);
            float ui = __shfl_sync(0xffffffffu, u,   i);
            uint4 q = cur[oi + lane];
            float2 c0 = __half22float2(*reinterpret_cast<__half2*>(&q.x));
            float2 c1 = __half22float2(*reinterpret_cast<__half2*>(&q.y));
            float2 c2 = __half22float2(*reinterpret_cast<__half2*>(&q.z));
            float2 c3 = __half22float2(*reinterpret_cast<__half2*>(&q.w));
            u64 u2 = pk2(ui, ui);
            u64 r = fma2(pk2(c3.x, c3.y), u2, pk2(c2.x, c2.y));
            r = fma2(r, u2, pk2(c1.x, c1.y));
            r = fma2(r, u2, pk2(c0.x, c0.y));
            acc[i] = add2(acc[i], r);
        }

        cp_async_wait0();
        __syncthreads();
    }

    // partials: part[dc][b][o]
    float* pdst = part + ((size_t)dc * BB + b0g + (w << 4)) * OO;
    #pragma unroll
    for (int i = 0; i < 16; i++) {
        float2 v = upk2(acc[i]);
        pdst[i * OO + lane]      = v.x;
        pdst[i * OO + 32 + lane] = v.y;
    }
}

// ---------------------------------------------------------------- split-K reduce + bias (float4)
__global__ void kan_reduce(const float* __restrict__ part, const float* __restrict__ bias,
                           float* __restrict__ out) {
    int idx = blockIdx.x * 256 + threadIdx.x;     // over B*O/4
    const float4* p4 = reinterpret_cast<const float4*>(part);
    float4 s = reinterpret_cast<const float4*>(bias)[idx & 15];
    #pragma unroll
    for (int c = 0; c < NDC; c++) {
        float4 v = p4[(size_t)c * (BB * OO / 4) + idx];
        s.x += v.x; s.y += v.y; s.z += v.z; s.w += v.w;
    }
    reinterpret_cast<float4*>(out)[idx] = s;
}

// ---------------------------------------------------------------- launch
extern "C" void kernel_launch(void* const* d_in, const int* in_sizes, int n_in,
                              void* d_out, int out_size) {
    const float* x      = (const float*)d_in[0];   // [8192, 64]
    const float* coeffs = (const float*)d_in[1];   // [64, 64, 64]
    const float* bias   = (const float*)d_in[2];   // [64]
    float* out = (float*)d_out;                    // [8192, 64]

    float* prt; cudaGetSymbolAddress((void**)&prt, g_part);

    const int smem_main = 2 * SLICE * 16 + DCH * BT * 4;   // 66560 + 16384 = 82944
    cudaFuncSetAttribute(kan_main, cudaFuncAttributeMaxDynamicSharedMemorySize, smem_main);

    kan_prep<<<DD, 256>>>(coeffs);
    kan_main<<<dim3(NBT, NDC), 512, smem_main>>>(x, prt);
    kan_reduce<<<(BB * OO / 4) / 256, 256>>>(prt, bias, out);
}

// round 5
// speedup vs baseline: 1.4426x; 1.1157x over previous
#include <cuda_runtime.h>
#include <cuda_fp16.h>
#include <cstdint>

// Problem constants: B=8192, O=64, D=64, K=64
#define BB   8192
#define OO   64
#define DD   64
#define KK   64
#define JJN  65                 // 0 = left-linear, 1..63 cubic, 64 = right-linear
#define SLICE (JJN * 32)        // uint4 entries per d-slice = 2080 (fp16-packed, o-pairs)
#define NDC  4                  // d-chunks (split-K)
#define DCH  (DD / NDC)         // 16
#define BT   256                // b-tile per CTA
#define NBT  (BB / BT)          // 32
#define JBLK 13                 // jj intervals per prep CTA (5 blocks cover 65)

typedef unsigned long long u64;

// Static device scratch
__device__ uint4 g_Ph[DD * SLICE];        // packed cubic coeffs, 2.13 MB
__device__ float g_part[NDC * BB * OO];   // split-K partials, 8 MB

// ---------------------------------------------------------------- asm helpers
__device__ __forceinline__ void cp_async16(uint32_t dst, const void* src) {
    asm volatile("cp.async.cg.shared.global [%0], [%1], 16;\n" :: "r"(dst), "l"(src));
}
__device__ __forceinline__ void cp_async_commit() { asm volatile("cp.async.commit_group;\n"); }
__device__ __forceinline__ void cp_async_wait0()  { asm volatile("cp.async.wait_group 0;\n"); }

__device__ __forceinline__ u64 pk2(float a, float b) {
    u64 r; asm("mov.b64 %0, {%1, %2};" : "=l"(r) : "f"(a), "f"(b)); return r;
}
__device__ __forceinline__ float2 upk2(u64 a) {
    float2 r; asm("mov.b64 {%0, %1}, %2;" : "=f"(r.x), "=f"(r.y) : "l"(a)); return r;
}
__device__ __forceinline__ u64 fma2(u64 a, u64 b, u64 c) {
    u64 d; asm("fma.rn.f32x2 %0, %1, %2, %3;" : "=l"(d) : "l"(a), "l"(b), "l"(c)); return d;
}
__device__ __forceinline__ u64 add2(u64 a, u64 b) {
    u64 d; asm("add.rn.f32x2 %0, %1, %2;" : "=l"(d) : "l"(a), "l"(b)); return d;
}

// ---------------------------------------------------------------- prep (parallelized on jj-blocks)
// grid (DD, 5), 512 threads. Each CTA emits jj in [lo, lo+12] for one d,
// computing only the slope/coeff k-window it needs. Matches reference PCHIP exactly.
__global__ __launch_bounds__(512) void kan_prep(const float* __restrict__ coeffs) {
    __shared__ float sy[16 * 65];   // y window, padded rows
    __shared__ float ss[14 * 64];   // slope window

    const int d  = blockIdx.x;
    const int lo = blockIdx.y * JBLK;            // first jj of this block (0,13,26,39,52)
    const int tid = threadIdx.x;
    const float inv_h = 15.75f;                  // 63/4 exact
    const float h = 4.0f / 63.0f;

    // k windows
    const int k0  = max(0, lo - 2);              // y rows [k0, k1]
    const int k1  = min(63, lo + JBLK);          // hi+1 where hi = lo+12
    const int nk  = k1 - k0 + 1;                 // <= 16
    const int ks0 = max(0, lo - 1);              // slope rows [ks0, ks1]
    const int ks1 = min(63, lo + JBLK - 1);
    const int nks = ks1 - ks0 + 1;               // <= 14

    // load y window: sy[(k-k0)*65 + o]  (16-float segments per o-row, L2-resident)
    for (int e = tid; e < OO * 16; e += 512) {
        int o = e >> 4, kk = e & 15;
        if (kk < nk)
            sy[kk * 65 + o] = coeffs[(o << 12) + (d << 6) + (k0 + kk)];
    }
    __syncthreads();

    // slopes for k in [ks0, ks1]
    for (int e = tid; e < OO * 16; e += 512) {
        int o = e >> 4, kk = e & 15;
        if (kk >= nks) continue;
        int k = ks0 + kk;
        float s;
        if (k == 0) {
            float d0 = (sy[(1 - k0) * 65 + o] - sy[(0 - k0) * 65 + o]) * inv_h;
            float d1 = (sy[(2 - k0) * 65 + o] - sy[(1 - k0) * 65 + o]) * inv_h;
            s = 0.5f * (3.0f * d0 - d1);
            if (s * d0 <= 0.0f) s = 0.0f;
            else if (d0 * d1 < 0.0f && fabsf(s) > 3.0f * fabsf(d0)) s = 3.0f * d0;
        } else if (k == 63) {
            float dN = (sy[(63 - k0) * 65 + o] - sy[(62 - k0) * 65 + o]) * inv_h;
            float dM = (sy[(62 - k0) * 65 + o] - sy[(61 - k0) * 65 + o]) * inv_h;
            s = 0.5f * (3.0f * dN - dM);
            if (s * dN <= 0.0f) s = 0.0f;
            else if (dN * dM < 0.0f && fabsf(s) > 3.0f * fabsf(dN)) s = 3.0f * dN;
        } else {
            float dp = (sy[(k - k0) * 65 + o]     - sy[(k - 1 - k0) * 65 + o]) * inv_h;
            float dn = (sy[(k + 1 - k0) * 65 + o] - sy[(k - k0) * 65 + o])     * inv_h;
            s = (dp * dn > 0.0f) ? (2.0f * dp * dn / (dp + dn + 1e-12f)) : 0.0f;
        }
        ss[kk * 64 + o] = s;
    }
    __syncthreads();

    // emit packed cubic coeffs for jj in [lo, min(64, lo+12)]
    auto evalP = [&](int jj, int o) -> float4 {
        float4 p;
        if (jj == 0) {
            p = make_float4(sy[(0 - k0) * 65 + o], h * ss[(0 - ks0) * 64 + o], 0.0f, 0.0f);
        } else if (jj == 64) {
            p = make_float4(sy[(63 - k0) * 65 + o], h * ss[(63 - ks0) * 64 + o], 0.0f, 0.0f);
        } else {
            int j = jj - 1;
            float y0 = sy[(j - k0) * 65 + o],       y1 = sy[(j + 1 - k0) * 65 + o];
            float m0 = h * ss[(j - ks0) * 64 + o],  m1 = h * ss[(j + 1 - ks0) * 64 + o];
            p.x = y0;
            p.y = m0;
            p.z = -3.0f * y0 + 3.0f * y1 - 2.0f * m0 - m1;
            p.w =  2.0f * y0 - 2.0f * y1 + m0 + m1;
        }
        return p;
    };

    uint4* Pd = g_Ph + d * SLICE;
    for (int e = tid; e < JBLK * 32; e += 512) {
        int jj = lo + (e >> 5), o = e & 31;
        if (jj > 64) continue;
        float4 a = evalP(jj, o);
        float4 b = evalP(jj, o + 32);
        __half2 h0 = __floats2half2_rn(a.x, b.x);
        __half2 h1 = __floats2half2_rn(a.y, b.y);
        __half2 h2 = __floats2half2_rn(a.z, b.z);
        __half2 h3 = __floats2half2_rn(a.w, b.w);
        uint4 q;
        q.x = *reinterpret_cast<uint32_t*>(&h0);
        q.y = *reinterpret_cast<uint32_t*>(&h1);
        q.z = *reinterpret_cast<uint32_t*>(&h2);
        q.w = *reinterpret_cast<uint32_t*>(&h3);
        Pd[(jj << 5) + o] = q;
    }
}

// ---------------------------------------------------------------- main contraction
// grid (NBT, NDC) = (32, 4) = 128 CTAs, 512 threads = 16 warps.
// Warp handles 16 b's; lanes index o-pair (o, o+32) via fp16-packed uint4 rows.
__global__ __launch_bounds__(512, 1) void kan_main(const float* __restrict__ x,
                                                   float* __restrict__ part) {
    extern __shared__ char smraw[];
    uint4* sP = reinterpret_cast<uint4*>(smraw);                  // 2 * SLICE uint4
    float* sx = reinterpret_cast<float*>(smraw + 2 * SLICE * 16); // DCH * BT floats

    const int bt = blockIdx.x, dc = blockIdx.y;
    const int tid = threadIdx.x;
    const int w = tid >> 5, lane = tid & 31;
    const int dbase = dc * DCH;
    const int b0g = bt * BT;

    // load x tile [BT][DCH] -> sx[dd][b_local]
    for (int e = tid; e < BT * 4; e += 512) {
        int bl = e >> 2, seg = e & 3;
        float4 v = *reinterpret_cast<const float4*>(x + (size_t)(b0g + bl) * DD + dbase + seg * 4);
        sx[(seg * 4 + 0) * BT + bl] = v.x;
        sx[(seg * 4 + 1) * BT + bl] = v.y;
        sx[(seg * 4 + 2) * BT + bl] = v.z;
        sx[(seg * 4 + 3) * BT + bl] = v.w;
    }

    uint32_t sb = (uint32_t)__cvta_generic_to_shared(sP);
    auto stage = [&](int dd, int which) {
        const uint4* src = g_Ph + (size_t)(dbase + dd) * SLICE;
        uint32_t dst = sb + (uint32_t)which * (SLICE * 16);
        for (int e = tid; e < SLICE; e += 512)
            cp_async16(dst + e * 16, src + e);
        cp_async_commit();
    };

    stage(0, 0);

    u64 acc[16];
    #pragma unroll
    for (int i = 0; i < 16; i++) acc[i] = 0ULL;   // bit pattern of (0.f, 0.f)

    cp_async_wait0();
    __syncthreads();   // covers sx stores too

    for (int dd = 0; dd < DCH; dd++) {
        uint4* cur = sP + (dd & 1) * SLICE;
        if (dd + 1 < DCH) stage(dd + 1, (dd + 1) & 1);

        // (jj, u) for this warp's 16 b's (lanes 16-31 mirror 0-15)
        float xv = sx[dd * BT + (w << 4) + (lane & 15)];
        float t = (xv + 2.0f) * 15.75f;
        float f = fminf(fmaxf(floorf(t), 0.0f), 62.0f);
        int jj; float u;
        if (t < 0.0f)       { jj = 0;  u = t; }
        else if (t > 63.0f) { jj = 64; u = t - 63.0f; }
        else                { jj = (int)f + 1; u = t - f; }
        int off = jj << 5;

        #pragma unroll
        for (int i = 0; i < 16; i++) {
            int   oi = __shfl_sync(0xffffffffu, off, i);
            float ui = __shfl_sync(0xffffffffu, u,   i);
            uint4 q = cur[oi + lane];
            float2 c0 = __half22float2(*reinterpret_cast<__half2*>(&q.x));
            float2 c1 = __half22float2(*reinterpret_cast<__half2*>(&q.y));
            float2 c2 = __half22float2(*reinterpret_cast<__half2*>(&q.z));
            float2 c3 = __half22float2(*reinterpret_cast<__half2*>(&q.w));
            u64 u2 = pk2(ui, ui);
            u64 r = fma2(pk2(c3.x, c3.y), u2, pk2(c2.x, c2.y));
            r = fma2(r, u2, pk2(c1.x, c1.y));
            r = fma2(r, u2, pk2(c0.x, c0.y));
            acc[i] = add2(acc[i], r);
        }

        cp_async_wait0();
        __syncthreads();
    }

    // partials: part[dc][b][o]
    float* pdst = part + ((size_t)dc * BB + b0g + (w << 4)) * OO;
    #pragma unroll
    for (int i = 0; i < 16; i++) {
        float2 v = upk2(acc[i]);
        pdst[i * OO + lane]      = v.x;
        pdst[i * OO + 32 + lane] = v.y;
    }
}

// ---------------------------------------------------------------- split-K reduce + bias (float4)
__global__ void kan_reduce(const float* __restrict__ part, const float* __restrict__ bias,
                           float* __restrict__ out) {
    int idx = blockIdx.x * 256 + threadIdx.x;     // over B*O/4
    const float4* p4 = reinterpret_cast<const float4*>(part);
    float4 s = reinterpret_cast<const float4*>(bias)[idx & 15];
    #pragma unroll
    for (int c = 0; c < NDC; c++) {
        float4 v = p4[(size_t)c * (BB * OO / 4) + idx];
        s.x += v.x; s.y += v.y; s.z += v.z; s.w += v.w;
    }
    reinterpret_cast<float4*>(out)[idx] = s;
}

// ---------------------------------------------------------------- launch
extern "C" void kernel_launch(void* const* d_in, const int* in_sizes, int n_in,
                              void* d_out, int out_size) {
    const float* x      = (const float*)d_in[0];   // [8192, 64]
    const float* coeffs = (const float*)d_in[1];   // [64, 64, 64]
    const float* bias   = (const float*)d_in[2];   // [64]
    float* out = (float*)d_out;                    // [8192, 64]

    float* prt; cudaGetSymbolAddress((void**)&prt, g_part);

    const int smem_main = 2 * SLICE * 16 + DCH * BT * 4;   // 66560 + 16384 = 82944
    cudaFuncSetAttribute(kan_main, cudaFuncAttributeMaxDynamicSharedMemorySize, smem_main);

    kan_prep<<<dim3(DD, 5), 512>>>(coeffs);
    kan_main<<<dim3(NBT, NDC), 512, smem_main>>>(x, prt);
    kan_reduce<<<(BB * OO / 4) / 256, 256>>>(prt, bias, out);
}

// round 6
// speedup vs baseline: 1.5477x; 1.0728x over previous
#include <cuda_runtime.h>
#include <cuda_fp16.h>
#include <cstdint>

// Problem constants: B=8192, O=64, D=64, K=64
#define BB   8192
#define OO   64
#define DD   64
#define KK   64
#define JJN  65                 // 0 = left-linear, 1..63 cubic, 64 = right-linear
#define SLICE (JJN * 32)        // uint4 entries per d-slice = 2080 (fp16-packed, o-pairs)
#define NDC  4                  // d-chunks (split-K)
#define DCH  (DD / NDC)         // 16
#define BT   256                // b-tile per CTA
#define NBT  (BB / BT)          // 32

typedef unsigned long long u64;

// Static device scratch
__device__ uint4 g_Ph[DD * SLICE];        // packed cubic coeffs, 2.13 MB
__device__ float g_part[NDC * BB * OO];   // split-K partials, 8 MB

// ---------------------------------------------------------------- asm helpers
__device__ __forceinline__ void cp_async16(uint32_t dst, const void* src) {
    asm volatile("cp.async.cg.shared.global [%0], [%1], 16;\n" :: "r"(dst), "l"(src));
}
__device__ __forceinline__ void cp_async_commit() { asm volatile("cp.async.commit_group;\n"); }
__device__ __forceinline__ void cp_async_wait0()  { asm volatile("cp.async.wait_group 0;\n"); }

__device__ __forceinline__ u64 pk2(float a, float b) {
    u64 r; asm("mov.b64 %0, {%1, %2};" : "=l"(r) : "f"(a), "f"(b)); return r;
}
__device__ __forceinline__ float2 upk2(u64 a) {
    float2 r; asm("mov.b64 {%0, %1}, %2;" : "=f"(r.x), "=f"(r.y) : "l"(a)); return r;
}
__device__ __forceinline__ u64 add2(u64 a, u64 b) {
    u64 d; asm("add.rn.f32x2 %0, %1, %2;" : "=l"(d) : "l"(a), "l"(b)); return d;
}

// ---------------------------------------------------------------- prep: warp per (d, jj)
// grid = 520 CTAs x 256 threads = 4160 warps = 64 d x 65 jj. No smem, no syncs.
// Each lane handles o = lane and o+32; exact reference PCHIP formulas.
__device__ __forceinline__ float pchip_end(float d0, float d1) {
    float s = 0.5f * (3.0f * d0 - d1);
    if (s * d0 <= 0.0f) s = 0.0f;
    else if (d0 * d1 < 0.0f && fabsf(s) > 3.0f * fabsf(d0)) s = 3.0f * d0;
    return s;
}
__device__ __forceinline__ float pchip_mid(float dp, float dn) {
    return (dp * dn > 0.0f) ? (2.0f * dp * dn / (dp + dn + 1e-12f)) : 0.0f;
}

__global__ __launch_bounds__(256) void kan_prep(const float* __restrict__ coeffs) {
    const int gw = blockIdx.x * 8 + (threadIdx.x >> 5);   // 0..4159
    const int lane = threadIdx.x & 31;
    const int d  = gw / JJN;
    const int jj = gw - d * JJN;

    const float inv_h = 15.75f;     // 63/4 exact
    const float h = 4.0f / 63.0f;

    // lane-uniform y-window start
    int start;
    if (jj == 0)       start = 0;
    else if (jj == 64) start = 60;
    else               start = min(max(jj - 2, 0), 60);

    const float* c0p = coeffs + (lane << 12)        + (d << 6) + start;
    const float* c1p = coeffs + ((lane + 32) << 12) + (d << 6) + start;
    // load both 4-float windows up front (MLP=8)
    float a0 = c0p[0], a1 = c0p[1], a2 = c0p[2], a3 = c0p[3];
    float b0 = c1p[0], b1 = c1p[1], b2 = c1p[2], b3 = c1p[3];

    auto emit = [&](float ya, float yb, float yc, float yd) -> float4 {
        float dab = (yb - ya) * inv_h;
        float dbc = (yc - yb) * inv_h;
        float dcd = (yd - yc) * inv_h;
        float4 p;
        if (jj == 0) {
            p = make_float4(ya, h * pchip_end(dab, dbc), 0.0f, 0.0f);
        } else if (jj == 64) {
            p = make_float4(yd, h * pchip_end(dcd, dbc), 0.0f, 0.0f);
        } else {
            float y0v, y1v, m0v, m1v;
            if (jj == 1)       { y0v = ya; y1v = yb; m0v = pchip_end(dab, dbc); m1v = pchip_mid(dab, dbc); }
            else if (jj == 63) { y0v = yc; y1v = yd; m0v = pchip_mid(dbc, dcd); m1v = pchip_end(dcd, dbc); }
            else               { y0v = yb; y1v = yc; m0v = pchip_mid(dab, dbc); m1v = pchip_mid(dbc, dcd); }
            float M0 = h * m0v, M1 = h * m1v;
            p.x = y0v;
            p.y = M0;
            p.z = -3.0f * y0v + 3.0f * y1v - 2.0f * M0 - M1;
            p.w =  2.0f * y0v - 2.0f * y1v + M0 + M1;
        }
        return p;
    };

    float4 pa = emit(a0, a1, a2, a3);
    float4 pb = emit(b0, b1, b2, b3);

    __half2 h0 = __floats2half2_rn(pa.x, pb.x);
    __half2 h1 = __floats2half2_rn(pa.y, pb.y);
    __half2 h2 = __floats2half2_rn(pa.z, pb.z);
    __half2 h3 = __floats2half2_rn(pa.w, pb.w);
    uint4 q;
    q.x = *reinterpret_cast<uint32_t*>(&h0);
    q.y = *reinterpret_cast<uint32_t*>(&h1);
    q.z = *reinterpret_cast<uint32_t*>(&h2);
    q.w = *reinterpret_cast<uint32_t*>(&h3);
    g_Ph[d * SLICE + (jj << 5) + lane] = q;
}

// ---------------------------------------------------------------- main contraction
// grid (NBT, NDC) = (32, 4) = 128 CTAs, 512 threads = 16 warps.
// Warp handles 16 b's; lanes index o-pair (o, o+32). Inner loop: 1 packed shuffle,
// LDS.128, HFMA2 Horner, single fp16->fp32 upgrade into f32x2 accumulator.
__global__ __launch_bounds__(512, 1) void kan_main(const float* __restrict__ x,
                                                   float* __restrict__ part) {
    extern __shared__ char smraw[];
    uint4* sP = reinterpret_cast<uint4*>(smraw);                  // 2 * SLICE uint4
    float* sx = reinterpret_cast<float*>(smraw + 2 * SLICE * 16); // DCH * BT floats

    const int bt = blockIdx.x, dc = blockIdx.y;
    const int tid = threadIdx.x;
    const int w = tid >> 5, lane = tid & 31;
    const int dbase = dc * DCH;
    const int b0g = bt * BT;

    // load x tile [BT][DCH] -> sx[dd][b_local]
    for (int e = tid; e < BT * 4; e += 512) {
        int bl = e >> 2, seg = e & 3;
        float4 v = *reinterpret_cast<const float4*>(x + (size_t)(b0g + bl) * DD + dbase + seg * 4);
        sx[(seg * 4 + 0) * BT + bl] = v.x;
        sx[(seg * 4 + 1) * BT + bl] = v.y;
        sx[(seg * 4 + 2) * BT + bl] = v.z;
        sx[(seg * 4 + 3) * BT + bl] = v.w;
    }

    uint32_t sb = (uint32_t)__cvta_generic_to_shared(sP);
    auto stage = [&](int dd, int which) {
        const uint4* src = g_Ph + (size_t)(dbase + dd) * SLICE;
        uint32_t dst = sb + (uint32_t)which * (SLICE * 16);
        for (int e = tid; e < SLICE; e += 512)
            cp_async16(dst + e * 16, src + e);
        cp_async_commit();
    };

    stage(0, 0);

    u64 acc[16];
    #pragma unroll
    for (int i = 0; i < 16; i++) acc[i] = 0ULL;   // bit pattern of (0.f, 0.f)

    cp_async_wait0();
    __syncthreads();   // covers sx stores too

    for (int dd = 0; dd < DCH; dd++) {
        uint4* cur = sP + (dd & 1) * SLICE;
        if (dd + 1 < DCH) stage(dd + 1, (dd + 1) & 1);

        // per-lane (jj, u) for this warp's 16 b's (lanes 16-31 mirror 0-15),
        // packed as (off << 16) | fp16(u)
        float xv = sx[dd * BT + (w << 4) + (lane & 15)];
        float t = (xv + 2.0f) * 15.75f;
        float f = fminf(fmaxf(floorf(t), 0.0f), 62.0f);
        int jj; float u;
        if (t < 0.0f)       { jj = 0;  u = t; }
        else if (t > 63.0f) { jj = 64; u = t - 63.0f; }
        else                { jj = (int)f + 1; u = t - f; }
        unsigned pk = ((unsigned)(jj << 5) << 16) |
                      (unsigned)__half_as_ushort(__float2half_rn(u));

        #pragma unroll
        for (int i = 0; i < 16; i++) {
            unsigned p  = __shfl_sync(0xffffffffu, pk, i);
            unsigned off = p >> 16;
            unsigned u2b = __byte_perm(p, p, 0x1010);     // half2(u, u)
            uint4 q = cur[off + lane];
            __half2 uu = *reinterpret_cast<__half2*>(&u2b);
            __half2 hc0 = *reinterpret_cast<__half2*>(&q.x);
            __half2 hc1 = *reinterpret_cast<__half2*>(&q.y);
            __half2 hc2 = *reinterpret_cast<__half2*>(&q.z);
            __half2 hc3 = *reinterpret_cast<__half2*>(&q.w);
            __half2 r = __hfma2(hc3, uu, hc2);
            r = __hfma2(r, uu, hc1);
            r = __hfma2(r, uu, hc0);
            float2 rf = __half22float2(r);
            acc[i] = add2(acc[i], pk2(rf.x, rf.y));
        }

        cp_async_wait0();
        __syncthreads();
    }

    // partials: part[dc][b][o]
    float* pdst = part + ((size_t)dc * BB + b0g + (w << 4)) * OO;
    #pragma unroll
    for (int i = 0; i < 16; i++) {
        float2 v = upk2(acc[i]);
        pdst[i * OO + lane]      = v.x;
        pdst[i * OO + 32 + lane] = v.y;
    }
}

// ---------------------------------------------------------------- split-K reduce + bias (float4)
__global__ void kan_reduce(const float* __restrict__ part, const float* __restrict__ bias,
                           float* __restrict__ out) {
    int idx = blockIdx.x * 256 + threadIdx.x;     // over B*O/4
    const float4* p4 = reinterpret_cast<const float4*>(part);
    float4 s = reinterpret_cast<const float4*>(bias)[idx & 15];
    #pragma unroll
    for (int c = 0; c < NDC; c++) {
        float4 v = p4[(size_t)c * (BB * OO / 4) + idx];
        s.x += v.x; s.y += v.y; s.z += v.z; s.w += v.w;
    }
    reinterpret_cast<float4*>(out)[idx] = s;
}

// ---------------------------------------------------------------- launch
extern "C" void kernel_launch(void* const* d_in, const int* in_sizes, int n_in,
                              void* d_out, int out_size) {
    const float* x      = (const float*)d_in[0];   // [8192, 64]
    const float* coeffs = (const float*)d_in[1];   // [64, 64, 64]
    const float* bias   = (const float*)d_in[2];   // [64]
    float* out = (float*)d_out;                    // [8192, 64]

    float* prt; cudaGetSymbolAddress((void**)&prt, g_part);

    const int smem_main = 2 * SLICE * 16 + DCH * BT * 4;   // 66560 + 16384 = 82944
    cudaFuncSetAttribute(kan_main, cudaFuncAttributeMaxDynamicSharedMemorySize, smem_main);

    kan_prep<<<(DD * JJN) / 8, 256>>>(coeffs);
    kan_main<<<dim3(NBT, NDC), 512, smem_main>>>(x, prt);
    kan_reduce<<<(BB * OO / 4) / 256, 256>>>(prt, bias, out);
}

// round 7
// speedup vs baseline: 1.7629x; 1.1390x over previous
#include <cuda_runtime.h>
#include <cuda_fp16.h>
#include <cstdint>

// Problem constants: B=8192, O=64, D=64, K=64
#define BB   8192
#define OO   64
#define DD   64
#define KK   64
#define JJN  65                 // 0 = left-linear, 1..63 cubic, 64 = right-linear
#define SLICE (JJN * 32)        // uint4 entries per d-slice = 2080 (fp16-packed, o-pairs)
#define SLICE_BYTES (SLICE * 16) // 33280
#define NDC  4                  // d-chunks (split-K)
#define DCH  (DD / NDC)         // 16
#define BT   256                // b-tile per CTA
#define NBT  (BB / BT)          // 32

typedef unsigned long long u64;

// Static device scratch
__device__ uint4 g_Ph[DD * SLICE];        // packed cubic coeffs, 2.13 MB
__device__ float g_part[NDC * BB * OO];   // split-K partials, 8 MB

// ---------------------------------------------------------------- asm helpers
__device__ __forceinline__ u64 pk2(float a, float b) {
    u64 r; asm("mov.b64 %0, {%1, %2};" : "=l"(r) : "f"(a), "f"(b)); return r;
}
__device__ __forceinline__ float2 upk2(u64 a) {
    float2 r; asm("mov.b64 {%0, %1}, %2;" : "=f"(r.x), "=f"(r.y) : "l"(a)); return r;
}
__device__ __forceinline__ u64 add2(u64 a, u64 b) {
    u64 d; asm("add.rn.f32x2 %0, %1, %2;" : "=l"(d) : "l"(a), "l"(b)); return d;
}
__device__ __forceinline__ void mbar_init(uint32_t mbar, uint32_t cnt) {
    asm volatile("mbarrier.init.shared.b64 [%0], %1;" :: "r"(mbar), "r"(cnt) : "memory");
}
__device__ __forceinline__ void mbar_expect_tx(uint32_t mbar, uint32_t bytes) {
    asm volatile("mbarrier.arrive.expect_tx.shared::cta.b64 _, [%0], %1;"
                 :: "r"(mbar), "r"(bytes) : "memory");
}
__device__ __forceinline__ void bulk_g2s(uint32_t dst, const void* src, uint32_t bytes,
                                         uint32_t mbar) {
    asm volatile("cp.async.bulk.shared::cta.global.mbarrier::complete_tx::bytes "
                 "[%0], [%1], %2, [%3];"
                 :: "r"(dst), "l"(src), "r"(bytes), "r"(mbar) : "memory");
}
__device__ __forceinline__ void mbar_wait(uint32_t mbar, uint32_t parity) {
    asm volatile(
        "{\n"
        ".reg .pred P;\n"
        "W%=:\n"
        "mbarrier.try_wait.parity.acquire.cta.shared::cta.b64 P, [%0], %1, 0x989680;\n"
        "@P bra D%=;\n"
        "bra W%=;\n"
        "D%=:\n"
        "}"
        :: "r"(mbar), "r"(parity) : "memory");
}

// ---------------------------------------------------------------- prep
// grid (DD, 9), 256 threads. CTA (d, blk) covers jj in [blk*8, blk*8+7] (clip at 64).
// One coalesced smem load of the 12-knot y-window, then one warp per jj computes
// the packed cubic using the exact reference PCHIP formulas.
__device__ __forceinline__ float pchip_end(float d0, float d1) {
    float s = 0.5f * (3.0f * d0 - d1);
    if (s * d0 <= 0.0f) s = 0.0f;
    else if (d0 * d1 < 0.0f && fabsf(s) > 3.0f * fabsf(d0)) s = 3.0f * d0;
    return s;
}
__device__ __forceinline__ float pchip_mid(float dp, float dn) {
    return (dp * dn > 0.0f) ? (2.0f * dp * dn / (dp + dn + 1e-12f)) : 0.0f;
}
__device__ __forceinline__ float4 pchip_emit(int jj, float ya, float yb, float yc, float yd) {
    const float inv_h = 15.75f;     // 63/4 exact
    const float h = 4.0f / 63.0f;
    float dab = (yb - ya) * inv_h;
    float dbc = (yc - yb) * inv_h;
    float dcd = (yd - yc) * inv_h;
    float4 p;
    if (jj == 0) {
        p = make_float4(ya, h * pchip_end(dab, dbc), 0.0f, 0.0f);
    } else if (jj == 64) {
        p = make_float4(yd, h * pchip_end(dcd, dbc), 0.0f, 0.0f);
    } else {
        float y0v, y1v, m0v, m1v;
        if (jj == 1)       { y0v = ya; y1v = yb; m0v = pchip_end(dab, dbc); m1v = pchip_mid(dab, dbc); }
        else if (jj == 63) { y0v = yc; y1v = yd; m0v = pchip_mid(dbc, dcd); m1v = pchip_end(dcd, dbc); }
        else               { y0v = yb; y1v = yc; m0v = pchip_mid(dab, dbc); m1v = pchip_mid(dbc, dcd); }
        float M0 = h * m0v, M1 = h * m1v;
        p.x = y0v;
        p.y = M0;
        p.z = -3.0f * y0v + 3.0f * y1v - 2.0f * M0 - M1;
        p.w =  2.0f * y0v - 2.0f * y1v + M0 + M1;
    }
    return p;
}

__global__ __launch_bounds__(256) void kan_prep(const float* __restrict__ coeffs) {
    __shared__ float sy[OO * 13];   // [o][kk] window, pad 13 (conflict-free lane reads)

    const int d   = blockIdx.x;
    const int blk = blockIdx.y;
    const int lo  = blk * 8;
    const int wlo = min(max(lo - 2, 0), 52);   // 12-knot window [wlo, wlo+11]

    // coalesced-segment load: 64 o-rows x 12 consecutive k
    for (int e = threadIdx.x; e < OO * 12; e += 256) {
        int o = e / 12, kk = e - o * 12;
        sy[o * 13 + kk] = coeffs[(o << 12) + (d << 6) + wlo + kk];
    }
    __syncthreads();

    const int wi = threadIdx.x >> 5, lane = threadIdx.x & 31;
    const int jj = lo + wi;
    if (jj > 64) return;

    int s = (jj == 0) ? 0 : ((jj == 64) ? 60 : min(max(jj - 2, 0), 60));
    int base = s - wlo;                         // in [0, 8]

    const float* r0 = &sy[lane * 13 + base];
    const float* r1 = &sy[(lane + 32) * 13 + base];
    float4 pa = pchip_emit(jj, r0[0], r0[1], r0[2], r0[3]);
    float4 pb = pchip_emit(jj, r1[0], r1[1], r1[2], r1[3]);

    __half2 h0 = __floats2half2_rn(pa.x, pb.x);
    __half2 h1 = __floats2half2_rn(pa.y, pb.y);
    __half2 h2 = __floats2half2_rn(pa.z, pb.z);
    __half2 h3 = __floats2half2_rn(pa.w, pb.w);
    uint4 q;
    q.x = *reinterpret_cast<uint32_t*>(&h0);
    q.y = *reinterpret_cast<uint32_t*>(&h1);
    q.z = *reinterpret_cast<uint32_t*>(&h2);
    q.w = *reinterpret_cast<uint32_t*>(&h3);
    g_Ph[d * SLICE + (jj << 5) + lane] = q;
}

// ---------------------------------------------------------------- main contraction
// grid (NBT, NDC) = (32, 4) = 128 CTAs, 512 threads = 16 warps.
// Warp handles 16 b's; lanes index o-pair (o, o+32). P slices staged by
// cp.async.bulk (one 33 KB DMA per dd) with mbarrier double buffering.
__global__ __launch_bounds__(512, 1) void kan_main(const float* __restrict__ x,
                                                   float* __restrict__ part) {
    extern __shared__ char smraw[];
    uint4* sP = reinterpret_cast<uint4*>(smraw);                      // 2 * SLICE uint4
    float* sx = reinterpret_cast<float*>(smraw + 2 * SLICE_BYTES);    // DCH * BT floats
    uint32_t mbarBase = (uint32_t)__cvta_generic_to_shared(
        smraw + 2 * SLICE_BYTES + DCH * BT * 4);                      // 2 x 8B mbarriers
    uint32_t sb = (uint32_t)__cvta_generic_to_shared(sP);

    const int bt = blockIdx.x, dc = blockIdx.y;
    const int tid = threadIdx.x;
    const int w = tid >> 5, lane = tid & 31;
    const int dbase = dc * DCH;
    const int b0g = bt * BT;

    // load x tile [BT][DCH] -> sx[dd][b_local]
    for (int e = tid; e < BT * 4; e += 512) {
        int bl = e >> 2, seg = e & 3;
        float4 v = *reinterpret_cast<const float4*>(x + (size_t)(b0g + bl) * DD + dbase + seg * 4);
        sx[(seg * 4 + 0) * BT + bl] = v.x;
        sx[(seg * 4 + 1) * BT + bl] = v.y;
        sx[(seg * 4 + 2) * BT + bl] = v.z;
        sx[(seg * 4 + 3) * BT + bl] = v.w;
    }

    if (tid == 0) {
        mbar_init(mbarBase, 1);
        mbar_init(mbarBase + 8, 1);
    }
    __syncthreads();   // mbar init visible + sx done

    auto issue = [&](int dd, int which) {
        uint32_t mb = mbarBase + (uint32_t)which * 8;
        mbar_expect_tx(mb, SLICE_BYTES);
        bulk_g2s(sb + (uint32_t)which * SLICE_BYTES,
                 g_Ph + (size_t)(dbase + dd) * SLICE, SLICE_BYTES, mb);
    };
    if (tid == 0) { issue(0, 0); issue(1, 1); }

    u64 acc[16];
    #pragma unroll
    for (int i = 0; i < 16; i++) acc[i] = 0ULL;   // bit pattern of (0.f, 0.f)

    uint32_t ph0 = 0, ph1 = 0;

    for (int dd = 0; dd < DCH; dd++) {
        int which = dd & 1;
        if (which == 0) { mbar_wait(mbarBase, ph0);     ph0 ^= 1; }
        else            { mbar_wait(mbarBase + 8, ph1); ph1 ^= 1; }
        uint4* cur = sP + which * SLICE;

        // per-lane (jj, u) for this warp's 16 b's (lanes 16-31 mirror 0-15),
        // packed as (off << 16) | fp16(u)
        float xv = sx[dd * BT + (w << 4) + (lane & 15)];
        float t = (xv + 2.0f) * 15.75f;
        float f = fminf(fmaxf(floorf(t), 0.0f), 62.0f);
        int jj; float u;
        if (t < 0.0f)       { jj = 0;  u = t; }
        else if (t > 63.0f) { jj = 64; u = t - 63.0f; }
        else                { jj = (int)f + 1; u = t - f; }
        unsigned pk = ((unsigned)(jj << 5) << 16) |
                      (unsigned)__half_as_ushort(__float2half_rn(u));

        #pragma unroll
        for (int i = 0; i < 16; i++) {
            unsigned p   = __shfl_sync(0xffffffffu, pk, i);
            unsigned off = p >> 16;
            unsigned u2b = __byte_perm(p, p, 0x1010);     // half2(u, u)
            uint4 q = cur[off + lane];
            __half2 uu = *reinterpret_cast<__half2*>(&u2b);
            __half2 hc0 = *reinterpret_cast<__half2*>(&q.x);
            __half2 hc1 = *reinterpret_cast<__half2*>(&q.y);
            __half2 hc2 = *reinterpret_cast<__half2*>(&q.z);
            __half2 hc3 = *reinterpret_cast<__half2*>(&q.w);
            __half2 r = __hfma2(hc3, uu, hc2);
            r = __hfma2(r, uu, hc1);
            r = __hfma2(r, uu, hc0);
            float2 rf = __half22float2(r);
            acc[i] = add2(acc[i], pk2(rf.x, rf.y));
        }

        __syncthreads();   // all warps done reading buffer `which`
        if (dd + 2 < DCH && tid == 0) issue(dd + 2, which);
    }

    // partials: part[dc][b][o]
    float* pdst = part + ((size_t)dc * BB + b0g + (w << 4)) * OO;
    #pragma unroll
    for (int i = 0; i < 16; i++) {
        float2 v = upk2(acc[i]);
        pdst[i * OO + lane]      = v.x;
        pdst[i * OO + 32 + lane] = v.y;
    }
}

// ---------------------------------------------------------------- split-K reduce + bias (float4)
__global__ void kan_reduce(const float* __restrict__ part, const float* __restrict__ bias,
                           float* __restrict__ out) {
    int idx = blockIdx.x * 256 + threadIdx.x;     // over B*O/4
    const float4* p4 = reinterpret_cast<const float4*>(part);
    float4 s = reinterpret_cast<const float4*>(bias)[idx & 15];
    #pragma unroll
    for (int c = 0; c < NDC; c++) {
        float4 v = p4[(size_t)c * (BB * OO / 4) + idx];
        s.x += v.x; s.y += v.y; s.z += v.z; s.w += v.w;
    }
    reinterpret_cast<float4*>(out)[idx] = s;
}

// ---------------------------------------------------------------- launch
extern "C" void kernel_launch(void* const* d_in, const int* in_sizes, int n_in,
                              void* d_out, int out_size) {
    const float* x      = (const float*)d_in[0];   // [8192, 64]
    const float* coeffs = (const float*)d_in[1];   // [64, 64, 64]
    const float* bias   = (const float*)d_in[2];   // [64]
    float* out = (float*)d_out;                    // [8192, 64]

    float* prt; cudaGetSymbolAddress((void**)&prt, g_part);

    const int smem_main = 2 * SLICE_BYTES + DCH * BT * 4 + 16;   // buffers + sx + mbars
    cudaFuncSetAttribute(kan_main, cudaFuncAttributeMaxDynamicSharedMemorySize, smem_main);

    kan_prep<<<dim3(DD, 9), 256>>>(coeffs);
    kan_main<<<dim3(NBT, NDC), 512, smem_main>>>(x, prt);
    kan_reduce<<<(BB * OO / 4) / 256, 256>>>(prt, bias, out);
}